// round 16
// baseline (speedup 1.0000x reference)
#include <cuda_runtime.h>
#include <cuda_fp16.h>
#include <mma.h>
#include <math_constants.h>

using namespace nvcuda;

// ---------------- scratch (device globals; no allocation allowed) ----------
#define NMAX 131072
#define EMAX 2097152   // >= E + 3*N padding
#define SENT (NMAX - 1)

__device__ __align__(16) __half2 g_u1h[NMAX * 32];   // u1 fp16, 32 half2/node
__device__ __align__(16) __half  g_h1h[NMAX * 64];   // h1 fp16
__device__ __align__(16) __half2 g_u2h[NMAX * 64];   // u2 fp16, 64 half2/node
__device__ __align__(16) __half  g_W2h[64 * 128];    // W2 rows 0..63 as fp16
__device__ int g_cnt[NMAX];          // zero at load; re-zeroed each pass
__device__ int g_off[NMAX];
__device__ int g_end[NMAX];          // padded end (off + ceil(cnt/4)*4)
__device__ int g_cur[NMAX];
__device__ int g_cursor;
__device__ __align__(16) int g_srcs[EMAX];

// grid barrier (count resets after each barrier; gen monotonic across replays)
__device__ unsigned g_bar_count = 0;
__device__ unsigned g_bar_gen = 0;

__device__ __forceinline__ void grid_barrier(unsigned G) {
    __syncthreads();
    if (threadIdx.x == 0) {
        __threadfence();
        unsigned gen = *(volatile unsigned*)&g_bar_gen;
        if (atomicAdd(&g_bar_count, 1u) == G - 1u) {
            atomicExch(&g_bar_count, 0u);
            __threadfence();
            atomicAdd(&g_bar_gen, 1u);
        } else {
            while (*(volatile unsigned*)&g_bar_gen == gen) __nanosleep(64);
        }
    }
    __syncthreads();
}

// ---------------- K1: prep + W2 cvt + alloc + scatter + agg1 -----------------
__global__ void __launch_bounds__(256) k_front(
        const float* __restrict__ x, const int* __restrict__ src,
        const int* __restrict__ dst,
        const float* __restrict__ W1, const float* __restrict__ b1,
        const float* __restrict__ W2,
        int n, int e, unsigned G) {
    __shared__ int wsum[8];
    __shared__ int sbase;
    int tid = threadIdx.x;
    int lane = tid & 31;
    unsigned stride = G * 256u;
    unsigned gtid0 = blockIdx.x * 256u + tid;

    // ---------- P1: u1 per node (fp16) + dst histogram + W2->fp16 + resets ---
    if (blockIdx.x == 0) {
        if (tid == 0) g_cursor = 0;
        if (tid < 32) ((unsigned*)g_u1h)[SENT * 32 + tid] = 0xFC00FC00u;
        if (tid < 64) ((unsigned*)g_u2h)[SENT * 64 + tid] = 0xFC00FC00u;
    }
    {
        unsigned t1 = (unsigned)n * 32u;
        unsigned t2 = t1 + (unsigned)e;
        unsigned total = t2 + 4096u;          // + W2 conversion work items
        for (unsigned i = gtid0; i < total; i += stride) {
            if (i < t1) {
                int node = i >> 5, p = i & 31;
                float x0 = x[node * 3 + 0], x1 = x[node * 3 + 1], x2 = x[node * 3 + 2];
                float u[2];
#pragma unroll
                for (int k = 0; k < 2; k++) {
                    int c = p * 2 + k;
                    float wa0 = W1[0 * 64 + c], wa1 = W1[1 * 64 + c], wa2 = W1[2 * 64 + c];
                    float wb0 = W1[3 * 64 + c], wb1 = W1[4 * 64 + c], wb2 = W1[5 * 64 + c];
                    u[k] = x0 * (wa0 + wb0) + x1 * (wa1 + wb1) + x2 * (wa2 + wb2) + b1[c];
                }
                g_u1h[i] = __floats2half2_rn(u[0], u[1]);
            } else if (i < t2) {
                atomicAdd(&g_cnt[dst[i - t1]], 1);
            } else {
                unsigned k = i - t2;          // 0..4095, converts W2[2k..2k+1]
                float2 w = *(const float2*)&W2[k * 2];
                ((__half2*)g_W2h)[k] = __floats2half2_rn(w.x, w.y);
            }
        }
    }
    grid_barrier(G);

    // ---------- P2: alloc ranges (block-aggregated cursor) + sentinel pads ---
    {
        int wid = tid >> 5;
        unsigned iters = ((unsigned)n + stride - 1) / stride;
        for (unsigned it = 0; it < iters; it++) {
            unsigned i = it * stride + gtid0;
            int c = 0;
            if (i < (unsigned)n) { c = g_cnt[i]; g_cnt[i] = 0; }
            int len = (c + 3) & ~3;
            int v = len;
#pragma unroll
            for (int o = 1; o < 32; o <<= 1) {
                int t = __shfl_up_sync(0xFFFFFFFFu, v, o);
                if (lane >= o) v += t;
            }
            if (lane == 31) wsum[wid] = v;
            __syncthreads();
            if (tid == 0) {
                int tot = 0;
#pragma unroll
                for (int w = 0; w < 8; w++) { int s = wsum[w]; wsum[w] = tot; tot += s; }
                sbase = atomicAdd(&g_cursor, tot);
            }
            __syncthreads();
            if (i < (unsigned)n) {
                int o = sbase + wsum[wid] + (v - len);
                g_off[i] = o;
                g_end[i] = o + len;
                g_cur[i] = o;
                for (int p = o + c; p < o + len; p++) g_srcs[p] = SENT;
            }
            __syncthreads();
        }
    }
    grid_barrier(G);

    // ---------- P3: scatter src ids into CSR ---------------------------------
    for (unsigned i = gtid0; i < (unsigned)e; i += stride) {
        int d = dst[i];
        int p = atomicAdd(&g_cur[d], 1);
        g_srcs[p] = src[i];
    }
    grid_barrier(G);

    // ---------- P4: layer-1 gather-max + relu -> h1 (fp16), warp per node ----
    {
        unsigned gwarp = gtid0 >> 5;
        unsigned nwarps = G * 8u;
        unsigned NEG = 0xFC00FC00u;
        int c0 = lane * 2, c1 = lane * 2 + 1;
        float wb00 = W1[3 * 64 + c0], wb01 = W1[4 * 64 + c0], wb02 = W1[5 * 64 + c0];
        float wb10 = W1[3 * 64 + c1], wb11 = W1[4 * 64 + c1], wb12 = W1[5 * 64 + c1];
        for (unsigned node = gwarp; node < (unsigned)n; node += nwarps) {
            int off = g_off[node], end = g_end[node];
            __half2 m = *(__half2*)&NEG;
            for (int j = off; j < end; j += 4) {
                int4 s = *(const int4*)&g_srcs[j];
                __half2 a = __ldcg(&g_u1h[s.x * 32 + lane]);
                __half2 b = __ldcg(&g_u1h[s.y * 32 + lane]);
                __half2 c = __ldcg(&g_u1h[s.z * 32 + lane]);
                __half2 d = __ldcg(&g_u1h[s.w * 32 + lane]);
                m = __hmax2(m, __hmax2(__hmax2(a, b), __hmax2(c, d)));
            }
            float2 mf = __half22float2(m);
            float x0 = x[node * 3 + 0], x1 = x[node * 3 + 1], x2 = x[node * 3 + 2];
            float v0 = x0 * wb00 + x1 * wb01 + x2 * wb02;
            float v1 = x0 * wb10 + x1 * wb11 + x2 * wb12;
            float h0 = fmaxf(mf.x - v0, 0.0f);
            float h1 = fmaxf(mf.y - v1, 0.0f);
            *(__half2*)&g_h1h[node * 64 + lane * 2] = __floats2half2_rn(h0, h1);
        }
    }
}

// ---------------- K2: persistent tensor-core GEMM ----------------------------
// U2 = H1@W2[0:64] + b2 + x@W2[64:67]. Each block stages fp16 W2 ONCE, then
// loops over 64-node tiles. Separate smem regions (no aliasing sync churn).
__global__ void __launch_bounds__(256) k_u2v2(
        const float* __restrict__ x, const float* __restrict__ W2,
        const float* __restrict__ b2, int n, int ntiles, int G2) {
    __shared__ __align__(16) __half sW2h[64 * 128];   // 16 KB, staged once
    __shared__ __align__(16) __half sH[64 * 64];      //  8 KB
    __shared__ __align__(16) float  sAcc[64 * 128];   // 32 KB
    __shared__ float sWx[3][128];
    __shared__ float sx[64][3];

    int t = threadIdx.x;
    int wid = t >> 5;

    // stage fp16 W2 (precomputed in k_front) + fp32 pos rows, once per block
    for (int i = t * 8; i < 8192; i += 2048)
        *(uint4*)&sW2h[i] = *(const uint4*)&g_W2h[i];
    if (t < 96) {
        int i = t * 4;
        *(float4*)&sWx[i >> 7][i & 127] = *(const float4*)&W2[64 * 128 + i];
    }

    int wm = wid & 3;
    int wn = wid >> 2;

    for (int tile = blockIdx.x; tile < ntiles; tile += G2) {
        int node0 = tile * 64;
        // load H tile (64x64 halves) + x tile
        for (int i = t; i < 512; i += 256) {
            int r = i >> 3, q = i & 7;
            int node = node0 + r;
            uint4 v = make_uint4(0u, 0u, 0u, 0u);
            if (node < n) v = *(const uint4*)&g_h1h[node * 64 + q * 8];
            *(uint4*)&sH[r * 64 + q * 8] = v;
        }
        if (t < 192) {
            int r = t / 3, c = t % 3;
            int node = node0 + r;
            sx[r][c] = (node < n) ? x[node * 3 + c] : 0.f;
        }
        __syncthreads();

        wmma::fragment<wmma::accumulator, 16, 16, 16, float> acc[4];
#pragma unroll
        for (int i = 0; i < 4; i++) wmma::fill_fragment(acc[i], 0.0f);
#pragma unroll
        for (int k = 0; k < 4; k++) {
            wmma::fragment<wmma::matrix_a, 16, 16, 16, __half, wmma::row_major> a;
            wmma::load_matrix_sync(a, sH + (wm * 16) * 64 + k * 16, 64);
#pragma unroll
            for (int nt = 0; nt < 4; nt++) {
                wmma::fragment<wmma::matrix_b, 16, 16, 16, __half, wmma::row_major> b;
                wmma::load_matrix_sync(b, sW2h + (k * 16) * 128 + wn * 64 + nt * 16, 128);
                wmma::mma_sync(acc[nt], a, b, acc[nt]);
            }
        }
#pragma unroll
        for (int nt = 0; nt < 4; nt++)
            wmma::store_matrix_sync(sAcc + (wm * 16) * 128 + wn * 64 + nt * 16,
                                    acc[nt], 128, wmma::mem_row_major);
        __syncthreads();

        for (int i = t * 4; i < 8192; i += 1024) {
            int r = i >> 7, c = i & 127;
            int node = node0 + r;
            if (node >= n) continue;
            float4 a4 = *(float4*)&sAcc[i];
            float x0 = sx[r][0], x1 = sx[r][1], x2 = sx[r][2];
            float4 vv;
            vv.x = x0 * sWx[0][c + 0] + x1 * sWx[1][c + 0] + x2 * sWx[2][c + 0];
            vv.y = x0 * sWx[0][c + 1] + x1 * sWx[1][c + 1] + x2 * sWx[2][c + 1];
            vv.z = x0 * sWx[0][c + 2] + x1 * sWx[1][c + 2] + x2 * sWx[2][c + 2];
            vv.w = x0 * sWx[0][c + 3] + x1 * sWx[1][c + 3] + x2 * sWx[2][c + 3];
            float4 bb = *(const float4*)&b2[c];
            __half2 u01 = __floats2half2_rn(a4.x + bb.x + vv.x, a4.y + bb.y + vv.y);
            __half2 u23 = __floats2half2_rn(a4.z + bb.z + vv.z, a4.w + bb.w + vv.w);
            uint2 upk;
            upk.x = *(unsigned*)&u01;
            upk.y = *(unsigned*)&u23;
            *(uint2*)&g_u2h[node * 64 + (c >> 1)] = upk;
        }
        __syncthreads();   // protect sH/sAcc before next tile
    }
}

// ---------------- K3: layer-2 gather-max + classifier head (warp/node) -------
__global__ void k_agg2out(const float* __restrict__ x, const float* __restrict__ W2,
                          const float* __restrict__ Wc, const float* __restrict__ bc,
                          float* __restrict__ out, int n) {
    int gt = blockIdx.x * blockDim.x + threadIdx.x;
    int node = gt >> 5, lane = gt & 31;
    if (node >= n) return;
    int off = g_off[node], end = g_end[node];
    unsigned NEG = 0xFC00FC00u;
    __half2 m0 = *(__half2*)&NEG, m1 = m0;
    for (int j = off; j < end; j += 4) {
        int4 s = *(const int4*)&g_srcs[j];
        uint2 ra = __ldcg((const uint2*)&g_u2h[s.x * 64 + lane * 2]);
        uint2 rb = __ldcg((const uint2*)&g_u2h[s.y * 64 + lane * 2]);
        uint2 rc = __ldcg((const uint2*)&g_u2h[s.z * 64 + lane * 2]);
        uint2 rd = __ldcg((const uint2*)&g_u2h[s.w * 64 + lane * 2]);
        m0 = __hmax2(m0, __hmax2(__hmax2(*(__half2*)&ra.x, *(__half2*)&rb.x),
                                 __hmax2(*(__half2*)&rc.x, *(__half2*)&rd.x)));
        m1 = __hmax2(m1, __hmax2(__hmax2(*(__half2*)&ra.y, *(__half2*)&rb.y),
                                 __hmax2(*(__half2*)&rc.y, *(__half2*)&rd.y)));
    }
    float2 f0 = __half22float2(m0);
    float2 f1 = __half22float2(m1);

    // recompute v2 for this node's 4 columns from x + W2 rows 64..66 (L1-hot)
    int c = lane * 4;
    float x0 = x[node * 3 + 0], x1 = x[node * 3 + 1], x2 = x[node * 3 + 2];
    float4 w64 = *(const float4*)&W2[64 * 128 + c];
    float4 w65 = *(const float4*)&W2[65 * 128 + c];
    float4 w66 = *(const float4*)&W2[66 * 128 + c];
    float4 vv;
    vv.x = x0 * w64.x + x1 * w65.x + x2 * w66.x;
    vv.y = x0 * w64.y + x1 * w65.y + x2 * w66.y;
    vv.z = x0 * w64.z + x1 * w65.z + x2 * w66.z;
    vv.w = x0 * w64.w + x1 * w65.w + x2 * w66.w;

    float h0 = fmaxf(f0.x - vv.x, 0.0f);
    float h1 = fmaxf(f0.y - vv.y, 0.0f);
    float h2 = fmaxf(f1.x - vv.z, 0.0f);
    float h3 = fmaxf(f1.y - vv.w, 0.0f);

    const float* w0 = Wc + (c + 0) * 5;
    const float* w1 = Wc + (c + 1) * 5;
    const float* w2 = Wc + (c + 2) * 5;
    const float* w3 = Wc + (c + 3) * 5;
    float a0 = h0 * w0[0] + h1 * w1[0] + h2 * w2[0] + h3 * w3[0];
    float a1 = h0 * w0[1] + h1 * w1[1] + h2 * w2[1] + h3 * w3[1];
    float a2 = h0 * w0[2] + h1 * w1[2] + h2 * w2[2] + h3 * w3[2];
    float a3 = h0 * w0[3] + h1 * w1[3] + h2 * w2[3] + h3 * w3[3];
    float a4 = h0 * w0[4] + h1 * w1[4] + h2 * w2[4] + h3 * w3[4];
#pragma unroll
    for (int o = 16; o; o >>= 1) {
        a0 += __shfl_xor_sync(0xFFFFFFFFu, a0, o);
        a1 += __shfl_xor_sync(0xFFFFFFFFu, a1, o);
        a2 += __shfl_xor_sync(0xFFFFFFFFu, a2, o);
        a3 += __shfl_xor_sync(0xFFFFFFFFu, a3, o);
        a4 += __shfl_xor_sync(0xFFFFFFFFu, a4, o);
    }
    if (lane == 0) {
        float l0 = a0 + bc[0], l1 = a1 + bc[1], l2 = a2 + bc[2];
        float l3 = a3 + bc[3], l4 = a4 + bc[4];
        float mm = fmaxf(fmaxf(fmaxf(l0, l1), fmaxf(l2, l3)), l4);
        float s = expf(l0 - mm) + expf(l1 - mm) + expf(l2 - mm) +
                  expf(l3 - mm) + expf(l4 - mm);
        float lse = mm + logf(s);
        float* o = out + node * 5;
        o[0] = l0 - lse; o[1] = l1 - lse; o[2] = l2 - lse;
        o[3] = l3 - lse; o[4] = l4 - lse;
    }
}

// ---------------- launch ------------------------------------------------------
extern "C" void kernel_launch(void* const* d_in, const int* in_sizes, int n_in,
                              void* d_out, int out_size) {
    const float* x  = (const float*)d_in[0];
    const int*   ei = (const int*)d_in[1];
    const float* W1 = (const float*)d_in[2];
    const float* b1 = (const float*)d_in[3];
    const float* W2 = (const float*)d_in[4];
    const float* b2 = (const float*)d_in[5];
    const float* Wc = (const float*)d_in[6];
    const float* bc = (const float*)d_in[7];
    float* out = (float*)d_out;

    int n = in_sizes[0] / 3;   // 100000
    int e = in_sizes[1] / 2;   // 1600000
    const int* src = ei;
    const int* dst = ei + e;

    int dev = 0;
    cudaGetDevice(&dev);
    int smCount = 0;
    cudaDeviceGetAttribute(&smCount, cudaDevAttrMultiProcessorCount, dev);
    if (smCount <= 0) smCount = 148;

    int nb = 0;
    cudaOccupancyMaxActiveBlocksPerMultiprocessor(&nb, k_front, 256, 0);
    if (nb < 1) nb = 1;
    if (nb > 8) nb = 8;
    unsigned G = (unsigned)smCount * (unsigned)nb;

    int ntiles = (n + 63) / 64;
    int nb2 = 0;
    cudaOccupancyMaxActiveBlocksPerMultiprocessor(&nb2, k_u2v2, 256, 0);
    if (nb2 < 1) nb2 = 1;
    if (nb2 > 4) nb2 = 4;
    int G2 = smCount * nb2;
    if (G2 > ntiles) G2 = ntiles;

    k_front  <<<G, 256>>>(x, src, dst, W1, b1, W2, n, e, G);
    k_u2v2   <<<G2, 256>>>(x, W2, b2, n, ntiles, G2);
    k_agg2out<<<(n * 32 + 255) / 256, 256>>>(x, W2, Wc, bc, out, n);
}

// round 17
// speedup vs baseline: 1.1245x; 1.1245x over previous
#include <cuda_runtime.h>
#include <cuda_fp16.h>
#include <mma.h>
#include <math_constants.h>

using namespace nvcuda;

// ---------------- scratch (device globals; no allocation allowed) ----------
#define NMAX 131072
#define EMAX 2097152   // >= E + 3*N padding
#define SENT (NMAX - 1)

__device__ __align__(16) __half2 g_u1h[NMAX * 32];   // u1 fp16, 32 half2/node
__device__ __align__(16) __half  g_h1h[NMAX * 64];   // h1 fp16
__device__ __align__(16) __half2 g_u2h[NMAX * 64];   // u2 fp16, 64 half2/node
__device__ int g_cnt[NMAX];          // zero at load; re-zeroed each pass
__device__ int g_off[NMAX];
__device__ int g_end[NMAX];          // padded end (off + ceil(cnt/4)*4)
__device__ int g_cur[NMAX];
__device__ int g_cursor;
__device__ __align__(16) int g_srcs[EMAX];

// grid barrier (count resets after each barrier; gen monotonic across replays)
__device__ unsigned g_bar_count = 0;
__device__ unsigned g_bar_gen = 0;

__device__ __forceinline__ void grid_barrier(unsigned G) {
    __syncthreads();
    if (threadIdx.x == 0) {
        __threadfence();
        unsigned gen = *(volatile unsigned*)&g_bar_gen;
        if (atomicAdd(&g_bar_count, 1u) == G - 1u) {
            atomicExch(&g_bar_count, 0u);
            __threadfence();
            atomicAdd(&g_bar_gen, 1u);
        } else {
            while (*(volatile unsigned*)&g_bar_gen == gen) __nanosleep(64);
        }
    }
    __syncthreads();
}

// ---------------- K1: prep + alloc + scatter + agg1 (EXACT R10 form) ---------
__global__ void __launch_bounds__(256) k_front(
        const float* __restrict__ x, const int* __restrict__ src,
        const int* __restrict__ dst,
        const float* __restrict__ W1, const float* __restrict__ b1,
        int n, int e, unsigned G) {
    __shared__ int wsum[8];
    __shared__ int sbase;
    int tid = threadIdx.x;
    int lane = tid & 31;
    unsigned stride = G * 256u;
    unsigned gtid0 = blockIdx.x * 256u + tid;

    // ---------- P1: u1 per node (fp16) + dst histogram + resets + sentinels --
    if (blockIdx.x == 0) {
        if (tid == 0) g_cursor = 0;
        if (tid < 32) ((unsigned*)g_u1h)[SENT * 32 + tid] = 0xFC00FC00u;
        if (tid < 64) ((unsigned*)g_u2h)[SENT * 64 + tid] = 0xFC00FC00u;
    }
    {
        unsigned t1 = (unsigned)n * 32u;
        unsigned total = t1 + (unsigned)e;
        for (unsigned i = gtid0; i < total; i += stride) {
            if (i < t1) {
                int node = i >> 5, p = i & 31;
                float x0 = x[node * 3 + 0], x1 = x[node * 3 + 1], x2 = x[node * 3 + 2];
                float u[2];
#pragma unroll
                for (int k = 0; k < 2; k++) {
                    int c = p * 2 + k;
                    float wa0 = W1[0 * 64 + c], wa1 = W1[1 * 64 + c], wa2 = W1[2 * 64 + c];
                    float wb0 = W1[3 * 64 + c], wb1 = W1[4 * 64 + c], wb2 = W1[5 * 64 + c];
                    u[k] = x0 * (wa0 + wb0) + x1 * (wa1 + wb1) + x2 * (wa2 + wb2) + b1[c];
                }
                g_u1h[i] = __floats2half2_rn(u[0], u[1]);
            } else {
                atomicAdd(&g_cnt[dst[i - t1]], 1);
            }
        }
    }
    grid_barrier(G);

    // ---------- P2: alloc ranges (block-aggregated cursor) + sentinel pads ---
    {
        int wid = tid >> 5;
        unsigned iters = ((unsigned)n + stride - 1) / stride;
        for (unsigned it = 0; it < iters; it++) {
            unsigned i = it * stride + gtid0;
            int c = 0;
            if (i < (unsigned)n) { c = g_cnt[i]; g_cnt[i] = 0; }
            int len = (c + 3) & ~3;
            int v = len;
#pragma unroll
            for (int o = 1; o < 32; o <<= 1) {
                int t = __shfl_up_sync(0xFFFFFFFFu, v, o);
                if (lane >= o) v += t;
            }
            if (lane == 31) wsum[wid] = v;
            __syncthreads();
            if (tid == 0) {
                int tot = 0;
#pragma unroll
                for (int w = 0; w < 8; w++) { int s = wsum[w]; wsum[w] = tot; tot += s; }
                sbase = atomicAdd(&g_cursor, tot);
            }
            __syncthreads();
            if (i < (unsigned)n) {
                int o = sbase + wsum[wid] + (v - len);
                g_off[i] = o;
                g_end[i] = o + len;
                g_cur[i] = o;
                for (int p = o + c; p < o + len; p++) g_srcs[p] = SENT;
            }
            __syncthreads();
        }
    }
    grid_barrier(G);

    // ---------- P3: scatter src ids into CSR ---------------------------------
    for (unsigned i = gtid0; i < (unsigned)e; i += stride) {
        int d = dst[i];
        int p = atomicAdd(&g_cur[d], 1);
        g_srcs[p] = src[i];
    }
    grid_barrier(G);

    // ---------- P4: layer-1 gather-max + relu -> h1 (fp16), warp per node ----
    {
        unsigned gwarp = gtid0 >> 5;
        unsigned nwarps = G * 8u;
        unsigned NEG = 0xFC00FC00u;
        int c0 = lane * 2, c1 = lane * 2 + 1;
        float wb00 = W1[3 * 64 + c0], wb01 = W1[4 * 64 + c0], wb02 = W1[5 * 64 + c0];
        float wb10 = W1[3 * 64 + c1], wb11 = W1[4 * 64 + c1], wb12 = W1[5 * 64 + c1];
        for (unsigned node = gwarp; node < (unsigned)n; node += nwarps) {
            int off = g_off[node], end = g_end[node];
            __half2 m = *(__half2*)&NEG;
            for (int j = off; j < end; j += 4) {
                int4 s = *(const int4*)&g_srcs[j];
                __half2 a = g_u1h[s.x * 32 + lane];
                __half2 b = g_u1h[s.y * 32 + lane];
                __half2 c = g_u1h[s.z * 32 + lane];
                __half2 d = g_u1h[s.w * 32 + lane];
                m = __hmax2(m, __hmax2(__hmax2(a, b), __hmax2(c, d)));
            }
            float2 mf = __half22float2(m);
            float x0 = x[node * 3 + 0], x1 = x[node * 3 + 1], x2 = x[node * 3 + 2];
            float v0 = x0 * wb00 + x1 * wb01 + x2 * wb02;
            float v1 = x0 * wb10 + x1 * wb11 + x2 * wb12;
            float h0 = fmaxf(mf.x - v0, 0.0f);
            float h1 = fmaxf(mf.y - v1, 0.0f);
            *(__half2*)&g_h1h[node * 64 + lane * 2] = __floats2half2_rn(h0, h1);
        }
    }
}

// ---------------- K2: persistent tensor-core GEMM ----------------------------
// U2 = H1@W2[0:64] + b2 + x@W2[64:67]. Each block stages + converts W2 ONCE,
// then loops over 64-node tiles. Separate smem regions for stage vs accumulate.
__global__ void __launch_bounds__(256) k_u2v2(
        const float* __restrict__ x, const float* __restrict__ W2,
        const float* __restrict__ b2, int n, int ntiles, int G2) {
    __shared__ __align__(16) __half sW2h[64 * 128];   // 16 KB, staged once
    __shared__ __align__(16) __half sH[64 * 64];      //  8 KB
    __shared__ __align__(16) float  sAcc[64 * 128];   // 32 KB
    __shared__ float sWx[3][128];
    __shared__ float sx[64][3];

    int t = threadIdx.x;
    int wid = t >> 5;

    // stage + convert W2 rows 0..63 once per block; fp32 pos rows 64..66
    for (int i = t * 4; i < 8192; i += 1024) {
        float4 w = *(const float4*)&W2[i];
        ((__half2*)sW2h)[i / 2]     = __floats2half2_rn(w.x, w.y);
        ((__half2*)sW2h)[i / 2 + 1] = __floats2half2_rn(w.z, w.w);
    }
    if (t < 96) {
        int i = t * 4;
        *(float4*)&sWx[i >> 7][i & 127] = *(const float4*)&W2[64 * 128 + i];
    }

    int wm = wid & 3;
    int wn = wid >> 2;

    for (int tile = blockIdx.x; tile < ntiles; tile += G2) {
        int node0 = tile * 64;
        for (int i = t; i < 512; i += 256) {
            int r = i >> 3, q = i & 7;
            int node = node0 + r;
            uint4 v = make_uint4(0u, 0u, 0u, 0u);
            if (node < n) v = *(const uint4*)&g_h1h[node * 64 + q * 8];
            *(uint4*)&sH[r * 64 + q * 8] = v;
        }
        if (t < 192) {
            int r = t / 3, c = t % 3;
            int node = node0 + r;
            sx[r][c] = (node < n) ? x[node * 3 + c] : 0.f;
        }
        __syncthreads();

        wmma::fragment<wmma::accumulator, 16, 16, 16, float> acc[4];
#pragma unroll
        for (int i = 0; i < 4; i++) wmma::fill_fragment(acc[i], 0.0f);
#pragma unroll
        for (int k = 0; k < 4; k++) {
            wmma::fragment<wmma::matrix_a, 16, 16, 16, __half, wmma::row_major> a;
            wmma::load_matrix_sync(a, sH + (wm * 16) * 64 + k * 16, 64);
#pragma unroll
            for (int nt = 0; nt < 4; nt++) {
                wmma::fragment<wmma::matrix_b, 16, 16, 16, __half, wmma::row_major> b;
                wmma::load_matrix_sync(b, sW2h + (k * 16) * 128 + wn * 64 + nt * 16, 128);
                wmma::mma_sync(acc[nt], a, b, acc[nt]);
            }
        }
#pragma unroll
        for (int nt = 0; nt < 4; nt++)
            wmma::store_matrix_sync(sAcc + (wm * 16) * 128 + wn * 64 + nt * 16,
                                    acc[nt], 128, wmma::mem_row_major);
        __syncthreads();

        for (int i = t * 4; i < 8192; i += 1024) {
            int r = i >> 7, c = i & 127;
            int node = node0 + r;
            if (node >= n) continue;
            float4 a4 = *(float4*)&sAcc[i];
            float x0 = sx[r][0], x1 = sx[r][1], x2 = sx[r][2];
            float4 vv;
            vv.x = x0 * sWx[0][c + 0] + x1 * sWx[1][c + 0] + x2 * sWx[2][c + 0];
            vv.y = x0 * sWx[0][c + 1] + x1 * sWx[1][c + 1] + x2 * sWx[2][c + 1];
            vv.z = x0 * sWx[0][c + 2] + x1 * sWx[1][c + 2] + x2 * sWx[2][c + 2];
            vv.w = x0 * sWx[0][c + 3] + x1 * sWx[1][c + 3] + x2 * sWx[2][c + 3];
            float4 bb = *(const float4*)&b2[c];
            __half2 u01 = __floats2half2_rn(a4.x + bb.x + vv.x, a4.y + bb.y + vv.y);
            __half2 u23 = __floats2half2_rn(a4.z + bb.z + vv.z, a4.w + bb.w + vv.w);
            uint2 upk;
            upk.x = *(unsigned*)&u01;
            upk.y = *(unsigned*)&u23;
            *(uint2*)&g_u2h[node * 64 + (c >> 1)] = upk;
        }
        __syncthreads();   // protect sH/sAcc before next tile
    }
}

// ---------------- K3: layer-2 gather-max + classifier head (EXACT R10 form) --
__global__ void k_agg2out(const float* __restrict__ x, const float* __restrict__ W2,
                          const float* __restrict__ Wc, const float* __restrict__ bc,
                          float* __restrict__ out, int n) {
    int gt = blockIdx.x * blockDim.x + threadIdx.x;
    int node = gt >> 5, lane = gt & 31;
    if (node >= n) return;
    int off = g_off[node], end = g_end[node];
    unsigned NEG = 0xFC00FC00u;
    __half2 m0 = *(__half2*)&NEG, m1 = m0;
    for (int j = off; j < end; j += 4) {
        int4 s = *(const int4*)&g_srcs[j];
        uint2 ra = *(const uint2*)&g_u2h[s.x * 64 + lane * 2];
        uint2 rb = *(const uint2*)&g_u2h[s.y * 64 + lane * 2];
        uint2 rc = *(const uint2*)&g_u2h[s.z * 64 + lane * 2];
        uint2 rd = *(const uint2*)&g_u2h[s.w * 64 + lane * 2];
        m0 = __hmax2(m0, __hmax2(__hmax2(*(__half2*)&ra.x, *(__half2*)&rb.x),
                                 __hmax2(*(__half2*)&rc.x, *(__half2*)&rd.x)));
        m1 = __hmax2(m1, __hmax2(__hmax2(*(__half2*)&ra.y, *(__half2*)&rb.y),
                                 __hmax2(*(__half2*)&rc.y, *(__half2*)&rd.y)));
    }
    float2 f0 = __half22float2(m0);
    float2 f1 = __half22float2(m1);

    // recompute v2 for this node's 4 columns from x + W2 rows 64..66 (L1-hot)
    int c = lane * 4;
    float x0 = x[node * 3 + 0], x1 = x[node * 3 + 1], x2 = x[node * 3 + 2];
    float4 w64 = *(const float4*)&W2[64 * 128 + c];
    float4 w65 = *(const float4*)&W2[65 * 128 + c];
    float4 w66 = *(const float4*)&W2[66 * 128 + c];
    float4 vv;
    vv.x = x0 * w64.x + x1 * w65.x + x2 * w66.x;
    vv.y = x0 * w64.y + x1 * w65.y + x2 * w66.y;
    vv.z = x0 * w64.z + x1 * w65.z + x2 * w66.z;
    vv.w = x0 * w64.w + x1 * w65.w + x2 * w66.w;

    float h0 = fmaxf(f0.x - vv.x, 0.0f);
    float h1 = fmaxf(f0.y - vv.y, 0.0f);
    float h2 = fmaxf(f1.x - vv.z, 0.0f);
    float h3 = fmaxf(f1.y - vv.w, 0.0f);

    const float* w0 = Wc + (c + 0) * 5;
    const float* w1 = Wc + (c + 1) * 5;
    const float* w2 = Wc + (c + 2) * 5;
    const float* w3 = Wc + (c + 3) * 5;
    float a0 = h0 * w0[0] + h1 * w1[0] + h2 * w2[0] + h3 * w3[0];
    float a1 = h0 * w0[1] + h1 * w1[1] + h2 * w2[1] + h3 * w3[1];
    float a2 = h0 * w0[2] + h1 * w1[2] + h2 * w2[2] + h3 * w3[2];
    float a3 = h0 * w0[3] + h1 * w1[3] + h2 * w2[3] + h3 * w3[3];
    float a4 = h0 * w0[4] + h1 * w1[4] + h2 * w2[4] + h3 * w3[4];
#pragma unroll
    for (int o = 16; o; o >>= 1) {
        a0 += __shfl_xor_sync(0xFFFFFFFFu, a0, o);
        a1 += __shfl_xor_sync(0xFFFFFFFFu, a1, o);
        a2 += __shfl_xor_sync(0xFFFFFFFFu, a2, o);
        a3 += __shfl_xor_sync(0xFFFFFFFFu, a3, o);
        a4 += __shfl_xor_sync(0xFFFFFFFFu, a4, o);
    }
    if (lane == 0) {
        float l0 = a0 + bc[0], l1 = a1 + bc[1], l2 = a2 + bc[2];
        float l3 = a3 + bc[3], l4 = a4 + bc[4];
        float mm = fmaxf(fmaxf(fmaxf(l0, l1), fmaxf(l2, l3)), l4);
        float s = expf(l0 - mm) + expf(l1 - mm) + expf(l2 - mm) +
                  expf(l3 - mm) + expf(l4 - mm);
        float lse = mm + logf(s);
        float* o = out + node * 5;
        o[0] = l0 - lse; o[1] = l1 - lse; o[2] = l2 - lse;
        o[3] = l3 - lse; o[4] = l4 - lse;
    }
}

// ---------------- launch ------------------------------------------------------
extern "C" void kernel_launch(void* const* d_in, const int* in_sizes, int n_in,
                              void* d_out, int out_size) {
    const float* x  = (const float*)d_in[0];
    const int*   ei = (const int*)d_in[1];
    const float* W1 = (const float*)d_in[2];
    const float* b1 = (const float*)d_in[3];
    const float* W2 = (const float*)d_in[4];
    const float* b2 = (const float*)d_in[5];
    const float* Wc = (const float*)d_in[6];
    const float* bc = (const float*)d_in[7];
    float* out = (float*)d_out;

    int n = in_sizes[0] / 3;   // 100000
    int e = in_sizes[1] / 2;   // 1600000
    const int* src = ei;
    const int* dst = ei + e;

    int dev = 0;
    cudaGetDevice(&dev);
    int smCount = 0;
    cudaDeviceGetAttribute(&smCount, cudaDevAttrMultiProcessorCount, dev);
    if (smCount <= 0) smCount = 148;

    int nb = 0;
    cudaOccupancyMaxActiveBlocksPerMultiprocessor(&nb, k_front, 256, 0);
    if (nb < 1) nb = 1;
    if (nb > 8) nb = 8;
    unsigned G = (unsigned)smCount * (unsigned)nb;

    int ntiles = (n + 63) / 64;
    int nb2 = 0;
    cudaOccupancyMaxActiveBlocksPerMultiprocessor(&nb2, k_u2v2, 256, 0);
    if (nb2 < 1) nb2 = 1;
    if (nb2 > 4) nb2 = 4;
    int G2 = smCount * nb2;
    if (G2 > ntiles) G2 = ntiles;

    k_front  <<<G, 256>>>(x, src, dst, W1, b1, n, e, G);
    k_u2v2   <<<G2, 256>>>(x, W2, b2, n, ntiles, G2);
    k_agg2out<<<(n * 32 + 255) / 256, 256>>>(x, W2, Wc, bc, out, n);
}